// round 8
// baseline (speedup 1.0000x reference)
#include <cuda_runtime.h>

#define RTHR 256
#define GRID 592              // 148 SMs x 4 resident blocks, guaranteed by launch_bounds

__device__ float g_part[GRID * 9];
__device__ unsigned int g_count;
__device__ volatile unsigned int g_gen;

// Legacy globals for the scalar fallback path
__device__ float g_B[9];
__device__ float g_ref[3];

// ---------------------------------------------------------------------------
// Compensated fp32 accumulation
// ---------------------------------------------------------------------------
struct KS { float s, c; };

__device__ __forceinline__ void ks_add(KS& a, float v) {
    float t  = a.s + v;
    float bp = t - a.s;
    float err = (a.s - (t - bp)) + (v - bp);
    a.c += err;
    a.s  = t;
}
__device__ __forceinline__ KS ks_comb(KS a, float s2, float c2) {
    float t  = a.s + s2;
    float bp = t - a.s;
    float err = (a.s - (t - bp)) + (s2 - bp);
    KS r; r.s = t; r.c = a.c + c2 + err;
    return r;
}

// ---------------------------------------------------------------------------
// Grid-wide barrier: sense-reversal via monotone generation + wrapping count.
// atomicInc wraps the counter back to 0 when the last block arrives, so the
// barrier is self-resetting across graph replays. gen is read BEFORE the
// increment, so the release (which requires our increment) cannot precede it.
// ---------------------------------------------------------------------------
__device__ __forceinline__ void grid_barrier() {
    __syncthreads();
    if (threadIdx.x == 0) {
        __threadfence();
        unsigned gen = g_gen;
        unsigned old = atomicInc(&g_count, GRID - 1);
        if (old == GRID - 1) {
            g_gen = gen + 1;           // release
        } else {
            while (g_gen == gen) { }   // spin (volatile read)
        }
    }
    __syncthreads();
    __threadfence();                   // acquire for g_part reads
}

// ---------------------------------------------------------------------------
// Shared eigensolve helper: from 9 fp64 sums -> basis (fp32) + ref
// ---------------------------------------------------------------------------
__device__ void solve_basis(const double* S, const float* __restrict__ x,
                            const float* __restrict__ axis, int T,
                            float* B /*9*/, float* ref /*3*/) {
    double invT = 1.0 / (double)T;
    double mu0 = S[0] * invT, mu1 = S[1] * invT, mu2 = S[2] * invT;
    double c00 = S[3] - S[0] * mu0;
    double c01 = S[4] - S[0] * mu1;
    double c02 = S[5] - S[0] * mu2;
    double c11 = S[6] - S[1] * mu1;
    double c12 = S[7] - S[1] * mu2;
    double c22 = S[8] - S[2] * mu2;

    double sh3 = (c00 + c11 + c22) * (1.0 / 3.0);
    double d00 = c00 - sh3, d11 = c11 - sh3, d22 = c22 - sh3;
    double mx = fabs(d00);
    if (fabs(d11) > mx) mx = fabs(d11);
    if (fabs(d22) > mx) mx = fabs(d22);
    if (fabs(c01) > mx) mx = fabs(c01);
    if (fabs(c02) > mx) mx = fabs(c02);
    if (fabs(c12) > mx) mx = fabs(c12);
    double inv = (mx > 0.0) ? (1.0 / mx) : 1.0;

    float A[3][3];
    A[0][0] = (float)(d00 * inv);
    A[1][1] = (float)(d11 * inv);
    A[2][2] = (float)(d22 * inv);
    A[0][1] = A[1][0] = (float)(c01 * inv);
    A[0][2] = A[2][0] = (float)(c02 * inv);
    A[1][2] = A[2][1] = (float)(c12 * inv);

    float V[3][3] = {{1,0,0},{0,1,0},{0,0,1}};
#pragma unroll 1
    for (int sweep = 0; sweep < 4; sweep++) {
        for (int p = 0; p < 2; p++)
            for (int q = p + 1; q < 3; q++) {
                float apq = A[p][q];
                if (fabsf(apq) < 1e-30f) continue;
                float tau = __fdividef(A[q][q] - A[p][p], 2.0f * apq);
                float t = __fdividef((tau >= 0.0f) ? 1.0f : -1.0f,
                                     fabsf(tau) + sqrtf(1.0f + tau * tau));
                float cth = rsqrtf(1.0f + t * t);
                float sth = t * cth;
                for (int r = 0; r < 3; r++) {
                    float arp = A[r][p], arq = A[r][q];
                    A[r][p] = cth * arp - sth * arq;
                    A[r][q] = sth * arp + cth * arq;
                }
                for (int cc = 0; cc < 3; cc++) {
                    float apc = A[p][cc], aqc = A[q][cc];
                    A[p][cc] = cth * apc - sth * aqc;
                    A[q][cc] = sth * apc + cth * aqc;
                }
                for (int r = 0; r < 3; r++) {
                    float vrp = V[r][p], vrq = V[r][q];
                    V[r][p] = cth * vrp - sth * vrq;
                    V[r][q] = sth * vrp + cth * vrq;
                }
            }
    }
    int im = 0;
    if (A[1][1] > A[0][0]) im = 1;
    if (A[2][2] > A[im][im]) im = 2;
    float zx = V[0][im], zy = V[1][im], zz = V[2][im];

    float qx = x[3 * (size_t)T];
    float qy = x[4 * (size_t)T];
    float qz = x[5 * (size_t)T];
    float qw = x[6 * (size_t)T];
    float fx = 2.0f * (qx * qz + qw * qy);
    float fy = 2.0f * (qy * qz - qw * qx);
    float fz = 1.0f - 2.0f * (qx * qx + qy * qy);
    if (fx * zx + fy * zy + fz * zz < 0.0f) { zx = -zx; zy = -zy; zz = -zz; }

    float ux = axis[0], uy = axis[1], uz = axis[2];
    float rx = uy * zz - uz * zy;
    float ry = uz * zx - ux * zz;
    float rz = ux * zy - uy * zx;
    float fwx = ry * uz - rz * uy;
    float fwy = rz * ux - rx * uz;
    float fwz = rx * uy - ry * ux;

    B[0] = rx;  B[1] = ry;  B[2] = rz;
    B[3] = ux;  B[4] = uy;  B[5] = uz;
    B[6] = fwx; B[7] = fwy; B[8] = fwz;
    ref[0] = x[0]; ref[1] = x[(size_t)T]; ref[2] = x[2 * (size_t)T];
}

// ---------------------------------------------------------------------------
// THE fused persistent kernel:
//   Phase 1: moments reduction over rows 0-2 (default cache -> L2 resident)
//            + Add copy rows 7-9 -> out rows 3-5 (ldcs/stcs, no pollution)
//   grid barrier
//   Per-block redundant solve (L2-only, all blocks in parallel, no 2nd bar)
//   Phase 2: transform rows 0-2 -> out rows 0-2 (Xpos reads hit L2)
// ---------------------------------------------------------------------------
__global__ void __launch_bounds__(RTHR, 4) fused_kernel(
        const float* __restrict__ x, const float* __restrict__ axis,
        float* __restrict__ out, int T) {
    int n4 = T >> 2;
    const float4* X = (const float4*)x;
    float4* O = (float4*)out;
    int tid = threadIdx.x;
    int gstride = GRID * RTHR;
    int g0 = blockIdx.x * RTHR + tid;

    // ---------------- Phase 1: reduce + copy ----------------
    float s[9];
#pragma unroll
    for (int k = 0; k < 9; k++) s[k] = 0.f;

    for (int i = g0; i < n4; i += gstride) {
        float4 a = X[i];
        float4 b = X[n4 + i];
        float4 c = X[2 * n4 + i];
        float4 d = __ldcs(&X[7 * n4 + i]);
        float4 e = __ldcs(&X[8 * n4 + i]);
        float4 f = __ldcs(&X[9 * n4 + i]);
        __stcs(&O[3 * n4 + i], d);
        __stcs(&O[4 * n4 + i], e);
        __stcs(&O[5 * n4 + i], f);
#define ACC(ax, bx, cx)                                   \
        s[0] += (ax); s[1] += (bx); s[2] += (cx);         \
        s[3] += (ax)*(ax); s[4] += (ax)*(bx);             \
        s[5] += (ax)*(cx); s[6] += (bx)*(bx);             \
        s[7] += (bx)*(cx); s[8] += (cx)*(cx);
        ACC(a.x, b.x, c.x); ACC(a.y, b.y, c.y);
        ACC(a.z, b.z, c.z); ACC(a.w, b.w, c.w);
#undef ACC
    }

    int lane = tid & 31, wid = tid >> 5;
#pragma unroll
    for (int off = 16; off; off >>= 1)
#pragma unroll
        for (int k = 0; k < 9; k++)
            s[k] += __shfl_down_sync(0xffffffffu, s[k], off);

    __shared__ float sh[RTHR / 32][9];
    if (lane == 0)
#pragma unroll
        for (int k = 0; k < 9; k++) sh[wid][k] = s[k];
    __syncthreads();
    if (wid == 0) {
#pragma unroll
        for (int k = 0; k < 9; k++)
            s[k] = (lane < RTHR / 32) ? sh[lane][k] : 0.f;
#pragma unroll
        for (int off = 4; off; off >>= 1)
#pragma unroll
            for (int k = 0; k < 9; k++)
                s[k] += __shfl_down_sync(0xffffffffu, s[k], off);
        if (lane == 0)
#pragma unroll
            for (int k = 0; k < 9; k++)
                g_part[blockIdx.x * 9 + k] = s[k];
    }

    // ---------------- Grid barrier ----------------
    grid_barrier();

    // ---------------- Redundant per-block solve ----------------
    KS acc[9];
#pragma unroll
    for (int k = 0; k < 9; k++) { acc[k].s = 0.f; acc[k].c = 0.f; }
    for (int b = tid; b < GRID; b += RTHR)
#pragma unroll
        for (int k = 0; k < 9; k++) ks_add(acc[k], __ldcg(&g_part[b * 9 + k]));

#pragma unroll
    for (int off = 16; off; off >>= 1)
#pragma unroll
        for (int k = 0; k < 9; k++) {
            float s2 = __shfl_down_sync(0xffffffffu, acc[k].s, off);
            float c2 = __shfl_down_sync(0xffffffffu, acc[k].c, off);
            acc[k] = ks_comb(acc[k], s2, c2);
        }

    __shared__ float shs[8][9], shc[8][9];
    __shared__ float sB[9], sref[3];
    if (lane == 0)
#pragma unroll
        for (int k = 0; k < 9; k++) { shs[wid][k] = acc[k].s; shc[wid][k] = acc[k].c; }
    __syncthreads();

    if (tid == 0) {
        double S[9];
#pragma unroll
        for (int k = 0; k < 9; k++) {
            double v = 0.0;
#pragma unroll
            for (int w = 0; w < 8; w++)
                v += (double)shs[w][k] + (double)shc[w][k];
            S[k] = v;
        }
        solve_basis(S, x, axis, T, sB, sref);
    }
    __syncthreads();

    float b00 = sB[0], b01 = sB[1], b02 = sB[2];
    float b10 = sB[3], b11 = sB[4], b12 = sB[5];
    float b20 = sB[6], b21 = sB[7], b22 = sB[8];
    float r0 = sref[0], r1 = sref[1], r2 = sref[2];

    // ---------------- Phase 2: transform (Xpos from L2) ----------------
    for (int i = g0; i < n4; i += gstride) {
        float4 p0 = X[i], p1 = X[n4 + i], p2 = X[2 * n4 + i];
        float4 o0, o1, o2;
#define TR(f) {                                           \
        float dx = p0.f - r0, dy = p1.f - r1, dz = p2.f - r2; \
        o0.f = b00 * dx + b01 * dy + b02 * dz;            \
        o1.f = b10 * dx + b11 * dy + b12 * dz;            \
        o2.f = b20 * dx + b21 * dy + b22 * dz; }
        TR(x); TR(y); TR(z); TR(w);
#undef TR
        __stcs(&O[i],          o0);
        __stcs(&O[n4 + i],     o1);
        __stcs(&O[2 * n4 + i], o2);
    }
}

// ---------------------------------------------------------------------------
// Scalar fallback path (T % 4 != 0): previous 3-kernel pipeline
// ---------------------------------------------------------------------------
__global__ void reduce_copy_sca_kernel(const float* __restrict__ x,
                                       float* __restrict__ out, int T) {
    size_t sT = (size_t)T;
    float s[9];
#pragma unroll
    for (int k = 0; k < 9; k++) s[k] = 0.f;
    for (int t = blockIdx.x * blockDim.x + threadIdx.x; t < T;
         t += gridDim.x * blockDim.x) {
        float ax = x[t], bx = x[sT + t], cx = x[2 * sT + t];
        s[0]+=ax; s[1]+=bx; s[2]+=cx; s[3]+=ax*ax; s[4]+=ax*bx;
        s[5]+=ax*cx; s[6]+=bx*bx; s[7]+=bx*cx; s[8]+=cx*cx;
        out[3 * sT + t] = x[7 * sT + t];
        out[4 * sT + t] = x[8 * sT + t];
        out[5 * sT + t] = x[9 * sT + t];
    }
    int lane = threadIdx.x & 31, wid = threadIdx.x >> 5;
#pragma unroll
    for (int off = 16; off; off >>= 1)
#pragma unroll
        for (int k = 0; k < 9; k++)
            s[k] += __shfl_down_sync(0xffffffffu, s[k], off);
    __shared__ float sh[RTHR / 32][9];
    if (lane == 0)
#pragma unroll
        for (int k = 0; k < 9; k++) sh[wid][k] = s[k];
    __syncthreads();
    if (wid == 0) {
#pragma unroll
        for (int k = 0; k < 9; k++)
            s[k] = (lane < RTHR / 32) ? sh[lane][k] : 0.f;
#pragma unroll
        for (int off = 4; off; off >>= 1)
#pragma unroll
            for (int k = 0; k < 9; k++)
                s[k] += __shfl_down_sync(0xffffffffu, s[k], off);
        if (lane == 0)
#pragma unroll
            for (int k = 0; k < 9; k++)
                g_part[blockIdx.x * 9 + k] = s[k];
    }
}

__global__ void solve_kernel(const float* __restrict__ x,
                             const float* __restrict__ axis, int T, int nblk) {
    int tid = threadIdx.x;
    KS acc[9];
#pragma unroll
    for (int k = 0; k < 9; k++) { acc[k].s = 0.f; acc[k].c = 0.f; }
    for (int b = tid; b < nblk; b += 256)
#pragma unroll
        for (int k = 0; k < 9; k++) ks_add(acc[k], g_part[b * 9 + k]);

    int lane = tid & 31, wid = tid >> 5;
#pragma unroll
    for (int off = 16; off; off >>= 1)
#pragma unroll
        for (int k = 0; k < 9; k++) {
            float s2 = __shfl_down_sync(0xffffffffu, acc[k].s, off);
            float c2 = __shfl_down_sync(0xffffffffu, acc[k].c, off);
            acc[k] = ks_comb(acc[k], s2, c2);
        }
    __shared__ float shs[8][9], shc[8][9];
    if (lane == 0)
#pragma unroll
        for (int k = 0; k < 9; k++) { shs[wid][k] = acc[k].s; shc[wid][k] = acc[k].c; }
    __syncthreads();
    if (tid == 0) {
        double S[9];
#pragma unroll
        for (int k = 0; k < 9; k++) {
            double v = 0.0;
#pragma unroll
            for (int w = 0; w < 8; w++)
                v += (double)shs[w][k] + (double)shc[w][k];
            S[k] = v;
        }
        float B[9], ref[3];
        solve_basis(S, x, axis, T, B, ref);
#pragma unroll
        for (int k = 0; k < 9; k++) g_B[k] = B[k];
#pragma unroll
        for (int k = 0; k < 3; k++) g_ref[k] = ref[k];
    }
}

__global__ void transform_sca_kernel(const float* __restrict__ x,
                                     float* __restrict__ out, int T) {
    size_t sT = (size_t)T;
    float b00 = g_B[0], b01 = g_B[1], b02 = g_B[2];
    float b10 = g_B[3], b11 = g_B[4], b12 = g_B[5];
    float b20 = g_B[6], b21 = g_B[7], b22 = g_B[8];
    float r0 = g_ref[0], r1 = g_ref[1], r2 = g_ref[2];
    for (int t = blockIdx.x * blockDim.x + threadIdx.x; t < T;
         t += gridDim.x * blockDim.x) {
        float dx = x[t] - r0, dy = x[sT + t] - r1, dz = x[2 * sT + t] - r2;
        out[t]          = b00 * dx + b01 * dy + b02 * dz;
        out[sT + t]     = b10 * dx + b11 * dy + b12 * dz;
        out[2 * sT + t] = b20 * dx + b21 * dy + b22 * dz;
    }
}

extern "C" void kernel_launch(void* const* d_in, const int* in_sizes, int n_in,
                              void* d_out, int out_size) {
    const float* x = (const float*)d_in[0];
    const float* axis = (const float*)d_in[1];
    int T = in_sizes[0] / 10;

    if ((T & 3) == 0) {
        fused_kernel<<<GRID, RTHR>>>(x, axis, (float*)d_out, T);
    } else {
        reduce_copy_sca_kernel<<<GRID, RTHR>>>(x, (float*)d_out, T);
        solve_kernel<<<1, 256>>>(x, axis, T, GRID);
        int blocks = (T + RTHR - 1) / RTHR;
        if (blocks > 16384) blocks = 16384;
        transform_sca_kernel<<<blocks, RTHR>>>(x, (float*)d_out, T);
    }
}

// round 12
// speedup vs baseline: 1.1364x; 1.1364x over previous
#include <cuda_runtime.h>

#define RBLK 2048
#define RTHR 256

__device__ float g_part[RBLK * 9];
__device__ unsigned int g_count;
__device__ float g_B[9];
__device__ float g_ref[3];

// ---------------------------------------------------------------------------
// Compensated fp32 accumulation
// ---------------------------------------------------------------------------
struct KS { float s, c; };

__device__ __forceinline__ void ks_add(KS& a, float v) {
    float t  = a.s + v;
    float bp = t - a.s;
    float err = (a.s - (t - bp)) + (v - bp);
    a.c += err;
    a.s  = t;
}
__device__ __forceinline__ KS ks_comb(KS a, float s2, float c2) {
    float t  = a.s + s2;
    float bp = t - a.s;
    float err = (a.s - (t - bp)) + (s2 - bp);
    KS r; r.s = t; r.c = a.c + c2 + err;
    return r;
}

// ---------------------------------------------------------------------------
// Eigensolve helper: 9 fp64 sums -> basis (fp32) + ref
// ---------------------------------------------------------------------------
__device__ void solve_basis(const double* S, const float* __restrict__ x,
                            const float* __restrict__ axis, int T,
                            float* B /*9*/, float* ref /*3*/) {
    double invT = 1.0 / (double)T;
    double mu0 = S[0] * invT, mu1 = S[1] * invT, mu2 = S[2] * invT;
    double c00 = S[3] - S[0] * mu0;
    double c01 = S[4] - S[0] * mu1;
    double c02 = S[5] - S[0] * mu2;
    double c11 = S[6] - S[1] * mu1;
    double c12 = S[7] - S[1] * mu2;
    double c22 = S[8] - S[2] * mu2;

    double sh3 = (c00 + c11 + c22) * (1.0 / 3.0);
    double d00 = c00 - sh3, d11 = c11 - sh3, d22 = c22 - sh3;
    double mx = fabs(d00);
    if (fabs(d11) > mx) mx = fabs(d11);
    if (fabs(d22) > mx) mx = fabs(d22);
    if (fabs(c01) > mx) mx = fabs(c01);
    if (fabs(c02) > mx) mx = fabs(c02);
    if (fabs(c12) > mx) mx = fabs(c12);
    double inv = (mx > 0.0) ? (1.0 / mx) : 1.0;

    float A[3][3];
    A[0][0] = (float)(d00 * inv);
    A[1][1] = (float)(d11 * inv);
    A[2][2] = (float)(d22 * inv);
    A[0][1] = A[1][0] = (float)(c01 * inv);
    A[0][2] = A[2][0] = (float)(c02 * inv);
    A[1][2] = A[2][1] = (float)(c12 * inv);

    float V[3][3] = {{1,0,0},{0,1,0},{0,0,1}};
#pragma unroll 1
    for (int sweep = 0; sweep < 4; sweep++) {
        for (int p = 0; p < 2; p++)
            for (int q = p + 1; q < 3; q++) {
                float apq = A[p][q];
                if (fabsf(apq) < 1e-30f) continue;
                float tau = __fdividef(A[q][q] - A[p][p], 2.0f * apq);
                float t = __fdividef((tau >= 0.0f) ? 1.0f : -1.0f,
                                     fabsf(tau) + sqrtf(1.0f + tau * tau));
                float cth = rsqrtf(1.0f + t * t);
                float sth = t * cth;
                for (int r = 0; r < 3; r++) {
                    float arp = A[r][p], arq = A[r][q];
                    A[r][p] = cth * arp - sth * arq;
                    A[r][q] = sth * arp + cth * arq;
                }
                for (int cc = 0; cc < 3; cc++) {
                    float apc = A[p][cc], aqc = A[q][cc];
                    A[p][cc] = cth * apc - sth * aqc;
                    A[q][cc] = sth * apc + cth * aqc;
                }
                for (int r = 0; r < 3; r++) {
                    float vrp = V[r][p], vrq = V[r][q];
                    V[r][p] = cth * vrp - sth * vrq;
                    V[r][q] = sth * vrp + cth * vrq;
                }
            }
    }
    int im = 0;
    if (A[1][1] > A[0][0]) im = 1;
    if (A[2][2] > A[im][im]) im = 2;
    float zx = V[0][im], zy = V[1][im], zz = V[2][im];

    float qx = x[3 * (size_t)T];
    float qy = x[4 * (size_t)T];
    float qz = x[5 * (size_t)T];
    float qw = x[6 * (size_t)T];
    float fx = 2.0f * (qx * qz + qw * qy);
    float fy = 2.0f * (qy * qz - qw * qx);
    float fz = 1.0f - 2.0f * (qx * qx + qy * qy);
    if (fx * zx + fy * zy + fz * zz < 0.0f) { zx = -zx; zy = -zy; zz = -zz; }

    float ux = axis[0], uy = axis[1], uz = axis[2];
    float rx = uy * zz - uz * zy;
    float ry = uz * zx - ux * zz;
    float rz = ux * zy - uy * zx;
    float fwx = ry * uz - rz * uy;
    float fwy = rz * ux - rx * uz;
    float fwz = rx * uy - ry * ux;

    B[0] = rx;  B[1] = ry;  B[2] = rz;
    B[3] = ux;  B[4] = uy;  B[5] = uz;
    B[6] = fwx; B[7] = fwy; B[8] = fwz;
    ref[0] = x[0]; ref[1] = x[(size_t)T]; ref[2] = x[2 * (size_t)T];
}

// ---------------------------------------------------------------------------
// Kernel 1: moments reduction (rows 0-2, __ldcg -> L2-resident) + Add copy
// (rows 7-9 -> out 3-5, ldcs/stcs) + LAST-BLOCK-DONE final solve.
// ---------------------------------------------------------------------------
__global__ void __launch_bounds__(RTHR) reduce_copy_solve_kernel(
        const float* __restrict__ x, const float* __restrict__ axis,
        float* __restrict__ out, int T) {
    int n4 = T >> 2;
    const float4* X = (const float4*)x;
    float4* O = (float4*)out;
    int tid = threadIdx.x;

    float s[9];
#pragma unroll
    for (int k = 0; k < 9; k++) s[k] = 0.f;

    for (int i = blockIdx.x * RTHR + tid; i < n4; i += RBLK * RTHR) {
        float4 a = __ldcg(&X[i]);
        float4 b = __ldcg(&X[n4 + i]);
        float4 c = __ldcg(&X[2 * n4 + i]);
        float4 d = __ldcs(&X[7 * n4 + i]);
        float4 e = __ldcs(&X[8 * n4 + i]);
        float4 f = __ldcs(&X[9 * n4 + i]);
        __stcs(&O[3 * n4 + i], d);
        __stcs(&O[4 * n4 + i], e);
        __stcs(&O[5 * n4 + i], f);
#define ACC(ax, bx, cx)                                   \
        s[0] += (ax); s[1] += (bx); s[2] += (cx);         \
        s[3] += (ax)*(ax); s[4] += (ax)*(bx);             \
        s[5] += (ax)*(cx); s[6] += (bx)*(bx);             \
        s[7] += (bx)*(cx); s[8] += (cx)*(cx);
        ACC(a.x, b.x, c.x); ACC(a.y, b.y, c.y);
        ACC(a.z, b.z, c.z); ACC(a.w, b.w, c.w);
#undef ACC
    }

    int lane = tid & 31, wid = tid >> 5;
#pragma unroll
    for (int off = 16; off; off >>= 1)
#pragma unroll
        for (int k = 0; k < 9; k++)
            s[k] += __shfl_down_sync(0xffffffffu, s[k], off);

    __shared__ float sh[RTHR / 32][9];
    if (lane == 0)
#pragma unroll
        for (int k = 0; k < 9; k++) sh[wid][k] = s[k];
    __syncthreads();
    if (wid == 0) {
#pragma unroll
        for (int k = 0; k < 9; k++)
            s[k] = (lane < RTHR / 32) ? sh[lane][k] : 0.f;
#pragma unroll
        for (int off = 4; off; off >>= 1)
#pragma unroll
            for (int k = 0; k < 9; k++)
                s[k] += __shfl_down_sync(0xffffffffu, s[k], off);
        if (lane == 0)
#pragma unroll
            for (int k = 0; k < 9; k++)
                g_part[blockIdx.x * 9 + k] = s[k];
    }

    // --- last-block-done: the final block to arrive performs the solve ---
    __shared__ int isLast;
    if (tid == 0) {
        __threadfence();
        unsigned old = atomicInc(&g_count, RBLK - 1);   // self-resetting
        isLast = (old == RBLK - 1);
    }
    __syncthreads();
    if (!isLast) return;

    KS acc[9];
#pragma unroll
    for (int k = 0; k < 9; k++) { acc[k].s = 0.f; acc[k].c = 0.f; }
    for (int b = tid; b < RBLK; b += RTHR)
#pragma unroll
        for (int k = 0; k < 9; k++) ks_add(acc[k], __ldcg(&g_part[b * 9 + k]));

#pragma unroll
    for (int off = 16; off; off >>= 1)
#pragma unroll
        for (int k = 0; k < 9; k++) {
            float s2 = __shfl_down_sync(0xffffffffu, acc[k].s, off);
            float c2 = __shfl_down_sync(0xffffffffu, acc[k].c, off);
            acc[k] = ks_comb(acc[k], s2, c2);
        }

    __shared__ float shs[8][9], shc[8][9];
    if (lane == 0)
#pragma unroll
        for (int k = 0; k < 9; k++) { shs[wid][k] = acc[k].s; shc[wid][k] = acc[k].c; }
    __syncthreads();

    if (tid == 0) {
        double S[9];
#pragma unroll
        for (int k = 0; k < 9; k++) {
            double v = 0.0;
#pragma unroll
            for (int w = 0; w < 8; w++)
                v += (double)shs[w][k] + (double)shc[w][k];
            S[k] = v;
        }
        float B[9], ref[3];
        solve_basis(S, x, axis, T, B, ref);
#pragma unroll
        for (int k = 0; k < 9; k++) g_B[k] = B[k];
#pragma unroll
        for (int k = 0; k < 3; k++) g_ref[k] = ref[k];
    }
}

// ---------------------------------------------------------------------------
// Kernel 2: transform rows 0-2 (Xpos via __ldcg, mostly L2 hits) -> out 0-2.
// ---------------------------------------------------------------------------
__global__ void __launch_bounds__(RTHR) transform_vec_kernel(
        const float* __restrict__ x, float* __restrict__ out, int T) {
    int n4 = T >> 2;
    int i = blockIdx.x * RTHR + threadIdx.x;
    if (i >= n4) return;

    float b00 = g_B[0], b01 = g_B[1], b02 = g_B[2];
    float b10 = g_B[3], b11 = g_B[4], b12 = g_B[5];
    float b20 = g_B[6], b21 = g_B[7], b22 = g_B[8];
    float r0 = g_ref[0], r1 = g_ref[1], r2 = g_ref[2];

    const float4* X = (const float4*)x;
    float4* O = (float4*)out;

    float4 p0 = __ldcg(&X[i]);
    float4 p1 = __ldcg(&X[n4 + i]);
    float4 p2 = __ldcg(&X[2 * n4 + i]);
    float4 o0, o1, o2;
#define TR(f) {                                           \
    float dx = p0.f - r0, dy = p1.f - r1, dz = p2.f - r2; \
    o0.f = b00 * dx + b01 * dy + b02 * dz;                \
    o1.f = b10 * dx + b11 * dy + b12 * dz;                \
    o2.f = b20 * dx + b21 * dy + b22 * dz; }
    TR(x); TR(y); TR(z); TR(w);
#undef TR
    __stcs(&O[i],          o0);
    __stcs(&O[n4 + i],     o1);
    __stcs(&O[2 * n4 + i], o2);
}

// ---------------------------------------------------------------------------
// Scalar fallback path (T % 4 != 0)
// ---------------------------------------------------------------------------
__global__ void reduce_copy_solve_sca_kernel(
        const float* __restrict__ x, const float* __restrict__ axis,
        float* __restrict__ out, int T) {
    size_t sT = (size_t)T;
    int tid = threadIdx.x;
    float s[9];
#pragma unroll
    for (int k = 0; k < 9; k++) s[k] = 0.f;
    for (int t = blockIdx.x * RTHR + tid; t < T; t += RBLK * RTHR) {
        float ax = x[t], bx = x[sT + t], cx = x[2 * sT + t];
        s[0]+=ax; s[1]+=bx; s[2]+=cx; s[3]+=ax*ax; s[4]+=ax*bx;
        s[5]+=ax*cx; s[6]+=bx*bx; s[7]+=bx*cx; s[8]+=cx*cx;
        out[3 * sT + t] = x[7 * sT + t];
        out[4 * sT + t] = x[8 * sT + t];
        out[5 * sT + t] = x[9 * sT + t];
    }
    int lane = tid & 31, wid = tid >> 5;
#pragma unroll
    for (int off = 16; off; off >>= 1)
#pragma unroll
        for (int k = 0; k < 9; k++)
            s[k] += __shfl_down_sync(0xffffffffu, s[k], off);
    __shared__ float sh[RTHR / 32][9];
    if (lane == 0)
#pragma unroll
        for (int k = 0; k < 9; k++) sh[wid][k] = s[k];
    __syncthreads();
    if (wid == 0) {
#pragma unroll
        for (int k = 0; k < 9; k++)
            s[k] = (lane < RTHR / 32) ? sh[lane][k] : 0.f;
#pragma unroll
        for (int off = 4; off; off >>= 1)
#pragma unroll
            for (int k = 0; k < 9; k++)
                s[k] += __shfl_down_sync(0xffffffffu, s[k], off);
        if (lane == 0)
#pragma unroll
            for (int k = 0; k < 9; k++)
                g_part[blockIdx.x * 9 + k] = s[k];
    }

    __shared__ int isLast;
    if (tid == 0) {
        __threadfence();
        unsigned old = atomicInc(&g_count, RBLK - 1);
        isLast = (old == RBLK - 1);
    }
    __syncthreads();
    if (!isLast) return;

    KS acc[9];
#pragma unroll
    for (int k = 0; k < 9; k++) { acc[k].s = 0.f; acc[k].c = 0.f; }
    for (int b = tid; b < RBLK; b += RTHR)
#pragma unroll
        for (int k = 0; k < 9; k++) ks_add(acc[k], __ldcg(&g_part[b * 9 + k]));
#pragma unroll
    for (int off = 16; off; off >>= 1)
#pragma unroll
        for (int k = 0; k < 9; k++) {
            float s2 = __shfl_down_sync(0xffffffffu, acc[k].s, off);
            float c2 = __shfl_down_sync(0xffffffffu, acc[k].c, off);
            acc[k] = ks_comb(acc[k], s2, c2);
        }
    __shared__ float shs[8][9], shc[8][9];
    if (lane == 0)
#pragma unroll
        for (int k = 0; k < 9; k++) { shs[wid][k] = acc[k].s; shc[wid][k] = acc[k].c; }
    __syncthreads();
    if (tid == 0) {
        double S[9];
#pragma unroll
        for (int k = 0; k < 9; k++) {
            double v = 0.0;
#pragma unroll
            for (int w = 0; w < 8; w++)
                v += (double)shs[w][k] + (double)shc[w][k];
            S[k] = v;
        }
        float B[9], ref[3];
        solve_basis(S, x, axis, T, B, ref);
#pragma unroll
        for (int k = 0; k < 9; k++) g_B[k] = B[k];
#pragma unroll
        for (int k = 0; k < 3; k++) g_ref[k] = ref[k];
    }
}

__global__ void transform_sca_kernel(const float* __restrict__ x,
                                     float* __restrict__ out, int T) {
    size_t sT = (size_t)T;
    float b00 = g_B[0], b01 = g_B[1], b02 = g_B[2];
    float b10 = g_B[3], b11 = g_B[4], b12 = g_B[5];
    float b20 = g_B[6], b21 = g_B[7], b22 = g_B[8];
    float r0 = g_ref[0], r1 = g_ref[1], r2 = g_ref[2];
    for (int t = blockIdx.x * blockDim.x + threadIdx.x; t < T;
         t += gridDim.x * blockDim.x) {
        float dx = x[t] - r0, dy = x[sT + t] - r1, dz = x[2 * sT + t] - r2;
        out[t]          = b00 * dx + b01 * dy + b02 * dz;
        out[sT + t]     = b10 * dx + b11 * dy + b12 * dz;
        out[2 * sT + t] = b20 * dx + b21 * dy + b22 * dz;
    }
}

extern "C" void kernel_launch(void* const* d_in, const int* in_sizes, int n_in,
                              void* d_out, int out_size) {
    const float* x = (const float*)d_in[0];
    const float* axis = (const float*)d_in[1];
    int T = in_sizes[0] / 10;

    if ((T & 3) == 0) {
        reduce_copy_solve_kernel<<<RBLK, RTHR>>>(x, axis, (float*)d_out, T);
        int n4 = T >> 2;
        int blocks = (n4 + RTHR - 1) / RTHR;
        transform_vec_kernel<<<blocks, RTHR>>>(x, (float*)d_out, T);
    } else {
        reduce_copy_solve_sca_kernel<<<RBLK, RTHR>>>(x, axis, (float*)d_out, T);
        int blocks = (T + RTHR - 1) / RTHR;
        if (blocks > 16384) blocks = 16384;
        transform_sca_kernel<<<blocks, RTHR>>>(x, (float*)d_out, T);
    }
}

// round 13
// speedup vs baseline: 1.3199x; 1.1615x over previous
#include <cuda_runtime.h>

#define RBLK 640          // 148 SMs x ~4.3; single wave at 5 blocks/SM (regs 48)
#define RTHR 256

__device__ float g_part[9 * RBLK];   // transposed: [k][block] -> coalesced solve reads
__device__ float g_B[9];
__device__ float g_ref[3];

// ---------------------------------------------------------------------------
// Compensated fp32 accumulation
// ---------------------------------------------------------------------------
struct KS { float s, c; };

__device__ __forceinline__ void ks_add(KS& a, float v) {
    float t  = a.s + v;
    float bp = t - a.s;
    float err = (a.s - (t - bp)) + (v - bp);
    a.c += err;
    a.s  = t;
}
__device__ __forceinline__ KS ks_comb(KS a, float s2, float c2) {
    float t  = a.s + s2;
    float bp = t - a.s;
    float err = (a.s - (t - bp)) + (s2 - bp);
    KS r; r.s = t; r.c = a.c + c2 + err;
    return r;
}

// ---------------------------------------------------------------------------
// Eigensolve helper: 9 fp64 sums -> basis (fp32) + ref
// ---------------------------------------------------------------------------
__device__ void solve_basis(const double* S, const float* __restrict__ x,
                            const float* __restrict__ axis, int T,
                            float* B /*9*/, float* ref /*3*/) {
    double invT = 1.0 / (double)T;
    double mu0 = S[0] * invT, mu1 = S[1] * invT, mu2 = S[2] * invT;
    double c00 = S[3] - S[0] * mu0;
    double c01 = S[4] - S[0] * mu1;
    double c02 = S[5] - S[0] * mu2;
    double c11 = S[6] - S[1] * mu1;
    double c12 = S[7] - S[1] * mu2;
    double c22 = S[8] - S[2] * mu2;

    double sh3 = (c00 + c11 + c22) * (1.0 / 3.0);
    double d00 = c00 - sh3, d11 = c11 - sh3, d22 = c22 - sh3;
    double mx = fabs(d00);
    if (fabs(d11) > mx) mx = fabs(d11);
    if (fabs(d22) > mx) mx = fabs(d22);
    if (fabs(c01) > mx) mx = fabs(c01);
    if (fabs(c02) > mx) mx = fabs(c02);
    if (fabs(c12) > mx) mx = fabs(c12);
    double inv = (mx > 0.0) ? (1.0 / mx) : 1.0;

    float A[3][3];
    A[0][0] = (float)(d00 * inv);
    A[1][1] = (float)(d11 * inv);
    A[2][2] = (float)(d22 * inv);
    A[0][1] = A[1][0] = (float)(c01 * inv);
    A[0][2] = A[2][0] = (float)(c02 * inv);
    A[1][2] = A[2][1] = (float)(c12 * inv);

    float V[3][3] = {{1,0,0},{0,1,0},{0,0,1}};
#pragma unroll 1
    for (int sweep = 0; sweep < 4; sweep++) {
        for (int p = 0; p < 2; p++)
            for (int q = p + 1; q < 3; q++) {
                float apq = A[p][q];
                if (fabsf(apq) < 1e-30f) continue;
                float tau = __fdividef(A[q][q] - A[p][p], 2.0f * apq);
                float t = __fdividef((tau >= 0.0f) ? 1.0f : -1.0f,
                                     fabsf(tau) + sqrtf(1.0f + tau * tau));
                float cth = rsqrtf(1.0f + t * t);
                float sth = t * cth;
                for (int r = 0; r < 3; r++) {
                    float arp = A[r][p], arq = A[r][q];
                    A[r][p] = cth * arp - sth * arq;
                    A[r][q] = sth * arp + cth * arq;
                }
                for (int cc = 0; cc < 3; cc++) {
                    float apc = A[p][cc], aqc = A[q][cc];
                    A[p][cc] = cth * apc - sth * aqc;
                    A[q][cc] = sth * apc + cth * aqc;
                }
                for (int r = 0; r < 3; r++) {
                    float vrp = V[r][p], vrq = V[r][q];
                    V[r][p] = cth * vrp - sth * vrq;
                    V[r][q] = sth * vrp + cth * vrq;
                }
            }
    }
    int im = 0;
    if (A[1][1] > A[0][0]) im = 1;
    if (A[2][2] > A[im][im]) im = 2;
    float zx = V[0][im], zy = V[1][im], zz = V[2][im];

    float qx = x[3 * (size_t)T];
    float qy = x[4 * (size_t)T];
    float qz = x[5 * (size_t)T];
    float qw = x[6 * (size_t)T];
    float fx = 2.0f * (qx * qz + qw * qy);
    float fy = 2.0f * (qy * qz - qw * qx);
    float fz = 1.0f - 2.0f * (qx * qx + qy * qy);
    if (fx * zx + fy * zy + fz * zz < 0.0f) { zx = -zx; zy = -zy; zz = -zz; }

    float ux = axis[0], uy = axis[1], uz = axis[2];
    float rx = uy * zz - uz * zy;
    float ry = uz * zx - ux * zz;
    float rz = ux * zy - uy * zx;
    float fwx = ry * uz - rz * uy;
    float fwy = rz * ux - rx * uz;
    float fwz = rx * uy - ry * ux;

    B[0] = rx;  B[1] = ry;  B[2] = rz;
    B[3] = ux;  B[4] = uy;  B[5] = uz;
    B[6] = fwx; B[7] = fwy; B[8] = fwz;
    ref[0] = x[0]; ref[1] = x[(size_t)T]; ref[2] = x[2 * (size_t)T];
}

// ---------------------------------------------------------------------------
// Kernel 1 (R6-proven): moments reduction over rows 0-2 (default cache ->
// L2-resident for k3) + Add copy rows 7-9 -> out rows 3-5 (ldcs/stcs).
// No solve code in this kernel (register isolation).
// ---------------------------------------------------------------------------
__global__ void __launch_bounds__(RTHR) reduce_copy_kernel(
        const float* __restrict__ x, float* __restrict__ out, int T) {
    int n4 = T >> 2;
    const float4* X = (const float4*)x;
    float4* O = (float4*)out;

    float s[9];
#pragma unroll
    for (int k = 0; k < 9; k++) s[k] = 0.f;

    for (int i = blockIdx.x * blockDim.x + threadIdx.x; i < n4;
         i += RBLK * RTHR) {
        float4 a = X[i];
        float4 b = X[n4 + i];
        float4 c = X[2 * n4 + i];
        float4 d = __ldcs(&X[7 * n4 + i]);
        float4 e = __ldcs(&X[8 * n4 + i]);
        float4 f = __ldcs(&X[9 * n4 + i]);
        __stcs(&O[3 * n4 + i], d);
        __stcs(&O[4 * n4 + i], e);
        __stcs(&O[5 * n4 + i], f);
#define ACC(ax, bx, cx)                                   \
        s[0] += (ax); s[1] += (bx); s[2] += (cx);         \
        s[3] += (ax)*(ax); s[4] += (ax)*(bx);             \
        s[5] += (ax)*(cx); s[6] += (bx)*(bx);             \
        s[7] += (bx)*(cx); s[8] += (cx)*(cx);
        ACC(a.x, b.x, c.x); ACC(a.y, b.y, c.y);
        ACC(a.z, b.z, c.z); ACC(a.w, b.w, c.w);
#undef ACC
    }

    int lane = threadIdx.x & 31, wid = threadIdx.x >> 5;
#pragma unroll
    for (int off = 16; off; off >>= 1)
#pragma unroll
        for (int k = 0; k < 9; k++)
            s[k] += __shfl_down_sync(0xffffffffu, s[k], off);

    __shared__ float sh[RTHR / 32][9];
    if (lane == 0)
#pragma unroll
        for (int k = 0; k < 9; k++) sh[wid][k] = s[k];
    __syncthreads();
    if (wid == 0) {
#pragma unroll
        for (int k = 0; k < 9; k++)
            s[k] = (lane < RTHR / 32) ? sh[lane][k] : 0.f;
#pragma unroll
        for (int off = 4; off; off >>= 1)
#pragma unroll
            for (int k = 0; k < 9; k++)
                s[k] += __shfl_down_sync(0xffffffffu, s[k], off);
        if (lane == 0)
#pragma unroll
            for (int k = 0; k < 9; k++)
                g_part[k * RBLK + blockIdx.x] = s[k];   // transposed write
    }
}

// ---------------------------------------------------------------------------
// Kernel 2: tiny solve. Coalesced partial reads (transposed layout):
// warp w handles component k = w % 9 ... actually simplest: each thread
// strides blocks for all 9 k with coalesced [k*RBLK + b] access.
// ---------------------------------------------------------------------------
__global__ void solve_kernel(const float* __restrict__ x,
                             const float* __restrict__ axis, int T) {
    int tid = threadIdx.x;
    KS acc[9];
#pragma unroll
    for (int k = 0; k < 9; k++) { acc[k].s = 0.f; acc[k].c = 0.f; }

    for (int b = tid; b < RBLK; b += 256)
#pragma unroll
        for (int k = 0; k < 9; k++)
            ks_add(acc[k], __ldcg(&g_part[k * RBLK + b]));   // coalesced per k

    int lane = tid & 31, wid = tid >> 5;
#pragma unroll
    for (int off = 16; off; off >>= 1)
#pragma unroll
        for (int k = 0; k < 9; k++) {
            float s2 = __shfl_down_sync(0xffffffffu, acc[k].s, off);
            float c2 = __shfl_down_sync(0xffffffffu, acc[k].c, off);
            acc[k] = ks_comb(acc[k], s2, c2);
        }

    __shared__ float shs[8][9], shc[8][9];
    if (lane == 0)
#pragma unroll
        for (int k = 0; k < 9; k++) { shs[wid][k] = acc[k].s; shc[wid][k] = acc[k].c; }
    __syncthreads();

    if (tid == 0) {
        double S[9];
#pragma unroll
        for (int k = 0; k < 9; k++) {
            double v = 0.0;
#pragma unroll
            for (int w = 0; w < 8; w++)
                v += (double)shs[w][k] + (double)shc[w][k];
            S[k] = v;
        }
        float B[9], ref[3];
        solve_basis(S, x, axis, T, B, ref);
#pragma unroll
        for (int k = 0; k < 9; k++) g_B[k] = B[k];
#pragma unroll
        for (int k = 0; k < 3; k++) g_ref[k] = ref[k];
    }
}

// ---------------------------------------------------------------------------
// Kernel 3 (R12-proven, 14.3us): transform rows 0-2 (Xpos via __ldcg,
// mostly L2 hits) -> out rows 0-2.
// ---------------------------------------------------------------------------
__global__ void __launch_bounds__(RTHR) transform_vec_kernel(
        const float* __restrict__ x, float* __restrict__ out, int T) {
    int n4 = T >> 2;
    int i = blockIdx.x * RTHR + threadIdx.x;
    if (i >= n4) return;

    float b00 = g_B[0], b01 = g_B[1], b02 = g_B[2];
    float b10 = g_B[3], b11 = g_B[4], b12 = g_B[5];
    float b20 = g_B[6], b21 = g_B[7], b22 = g_B[8];
    float r0 = g_ref[0], r1 = g_ref[1], r2 = g_ref[2];

    const float4* X = (const float4*)x;
    float4* O = (float4*)out;

    float4 p0 = __ldcg(&X[i]);
    float4 p1 = __ldcg(&X[n4 + i]);
    float4 p2 = __ldcg(&X[2 * n4 + i]);
    float4 o0, o1, o2;
#define TR(f) {                                           \
    float dx = p0.f - r0, dy = p1.f - r1, dz = p2.f - r2; \
    o0.f = b00 * dx + b01 * dy + b02 * dz;                \
    o1.f = b10 * dx + b11 * dy + b12 * dz;                \
    o2.f = b20 * dx + b21 * dy + b22 * dz; }
    TR(x); TR(y); TR(z); TR(w);
#undef TR
    __stcs(&O[i],          o0);
    __stcs(&O[n4 + i],     o1);
    __stcs(&O[2 * n4 + i], o2);
}

// ---------------------------------------------------------------------------
// Scalar fallback path (T % 4 != 0)
// ---------------------------------------------------------------------------
__global__ void reduce_copy_sca_kernel(const float* __restrict__ x,
                                       float* __restrict__ out, int T) {
    size_t sT = (size_t)T;
    float s[9];
#pragma unroll
    for (int k = 0; k < 9; k++) s[k] = 0.f;
    for (int t = blockIdx.x * blockDim.x + threadIdx.x; t < T;
         t += RBLK * RTHR) {
        float ax = x[t], bx = x[sT + t], cx = x[2 * sT + t];
        s[0]+=ax; s[1]+=bx; s[2]+=cx; s[3]+=ax*ax; s[4]+=ax*bx;
        s[5]+=ax*cx; s[6]+=bx*bx; s[7]+=bx*cx; s[8]+=cx*cx;
        out[3 * sT + t] = x[7 * sT + t];
        out[4 * sT + t] = x[8 * sT + t];
        out[5 * sT + t] = x[9 * sT + t];
    }
    int lane = threadIdx.x & 31, wid = threadIdx.x >> 5;
#pragma unroll
    for (int off = 16; off; off >>= 1)
#pragma unroll
        for (int k = 0; k < 9; k++)
            s[k] += __shfl_down_sync(0xffffffffu, s[k], off);
    __shared__ float sh[RTHR / 32][9];
    if (lane == 0)
#pragma unroll
        for (int k = 0; k < 9; k++) sh[wid][k] = s[k];
    __syncthreads();
    if (wid == 0) {
#pragma unroll
        for (int k = 0; k < 9; k++)
            s[k] = (lane < RTHR / 32) ? sh[lane][k] : 0.f;
#pragma unroll
        for (int off = 4; off; off >>= 1)
#pragma unroll
            for (int k = 0; k < 9; k++)
                s[k] += __shfl_down_sync(0xffffffffu, s[k], off);
        if (lane == 0)
#pragma unroll
            for (int k = 0; k < 9; k++)
                g_part[k * RBLK + blockIdx.x] = s[k];
    }
}

__global__ void transform_sca_kernel(const float* __restrict__ x,
                                     float* __restrict__ out, int T) {
    size_t sT = (size_t)T;
    float b00 = g_B[0], b01 = g_B[1], b02 = g_B[2];
    float b10 = g_B[3], b11 = g_B[4], b12 = g_B[5];
    float b20 = g_B[6], b21 = g_B[7], b22 = g_B[8];
    float r0 = g_ref[0], r1 = g_ref[1], r2 = g_ref[2];
    for (int t = blockIdx.x * blockDim.x + threadIdx.x; t < T;
         t += gridDim.x * blockDim.x) {
        float dx = x[t] - r0, dy = x[sT + t] - r1, dz = x[2 * sT + t] - r2;
        out[t]          = b00 * dx + b01 * dy + b02 * dz;
        out[sT + t]     = b10 * dx + b11 * dy + b12 * dz;
        out[2 * sT + t] = b20 * dx + b21 * dy + b22 * dz;
    }
}

extern "C" void kernel_launch(void* const* d_in, const int* in_sizes, int n_in,
                              void* d_out, int out_size) {
    const float* x = (const float*)d_in[0];
    const float* axis = (const float*)d_in[1];
    int T = in_sizes[0] / 10;

    if ((T & 3) == 0) {
        reduce_copy_kernel<<<RBLK, RTHR>>>(x, (float*)d_out, T);
        solve_kernel<<<1, 256>>>(x, axis, T);
        int n4 = T >> 2;
        int blocks = (n4 + RTHR - 1) / RTHR;
        transform_vec_kernel<<<blocks, RTHR>>>(x, (float*)d_out, T);
    } else {
        reduce_copy_sca_kernel<<<RBLK, RTHR>>>(x, (float*)d_out, T);
        solve_kernel<<<1, 256>>>(x, axis, T);
        int blocks = (T + RTHR - 1) / RTHR;
        if (blocks > 16384) blocks = 16384;
        transform_sca_kernel<<<blocks, RTHR>>>(x, (float*)d_out, T);
    }
}

// round 14
// speedup vs baseline: 1.5453x; 1.1708x over previous
#include <cuda_runtime.h>

#define RBLK 2048
#define RTHR 256

__device__ float g_part[9 * RBLK];   // transposed: [k][block] -> coalesced solve reads
__device__ float g_B[9];
__device__ float g_ref[3];

// ---------------------------------------------------------------------------
// Compensated fp32 accumulation
// ---------------------------------------------------------------------------
struct KS { float s, c; };

__device__ __forceinline__ void ks_add(KS& a, float v) {
    float t  = a.s + v;
    float bp = t - a.s;
    float err = (a.s - (t - bp)) + (v - bp);
    a.c += err;
    a.s  = t;
}
__device__ __forceinline__ KS ks_comb(KS a, float s2, float c2) {
    float t  = a.s + s2;
    float bp = t - a.s;
    float err = (a.s - (t - bp)) + (s2 - bp);
    KS r; r.s = t; r.c = a.c + c2 + err;
    return r;
}

// ---------------------------------------------------------------------------
// Eigensolve helper: 9 fp64 sums -> basis (fp32) + ref
// ---------------------------------------------------------------------------
__device__ void solve_basis(const double* S, const float* __restrict__ x,
                            const float* __restrict__ axis, int T,
                            float* B /*9*/, float* ref /*3*/) {
    double invT = 1.0 / (double)T;
    double mu0 = S[0] * invT, mu1 = S[1] * invT, mu2 = S[2] * invT;
    double c00 = S[3] - S[0] * mu0;
    double c01 = S[4] - S[0] * mu1;
    double c02 = S[5] - S[0] * mu2;
    double c11 = S[6] - S[1] * mu1;
    double c12 = S[7] - S[1] * mu2;
    double c22 = S[8] - S[2] * mu2;

    double sh3 = (c00 + c11 + c22) * (1.0 / 3.0);
    double d00 = c00 - sh3, d11 = c11 - sh3, d22 = c22 - sh3;
    double mx = fabs(d00);
    if (fabs(d11) > mx) mx = fabs(d11);
    if (fabs(d22) > mx) mx = fabs(d22);
    if (fabs(c01) > mx) mx = fabs(c01);
    if (fabs(c02) > mx) mx = fabs(c02);
    if (fabs(c12) > mx) mx = fabs(c12);
    double inv = (mx > 0.0) ? (1.0 / mx) : 1.0;

    float A[3][3];
    A[0][0] = (float)(d00 * inv);
    A[1][1] = (float)(d11 * inv);
    A[2][2] = (float)(d22 * inv);
    A[0][1] = A[1][0] = (float)(c01 * inv);
    A[0][2] = A[2][0] = (float)(c02 * inv);
    A[1][2] = A[2][1] = (float)(c12 * inv);

    float V[3][3] = {{1,0,0},{0,1,0},{0,0,1}};
#pragma unroll 1
    for (int sweep = 0; sweep < 4; sweep++) {
        for (int p = 0; p < 2; p++)
            for (int q = p + 1; q < 3; q++) {
                float apq = A[p][q];
                if (fabsf(apq) < 1e-30f) continue;
                float tau = __fdividef(A[q][q] - A[p][p], 2.0f * apq);
                float t = __fdividef((tau >= 0.0f) ? 1.0f : -1.0f,
                                     fabsf(tau) + sqrtf(1.0f + tau * tau));
                float cth = rsqrtf(1.0f + t * t);
                float sth = t * cth;
                for (int r = 0; r < 3; r++) {
                    float arp = A[r][p], arq = A[r][q];
                    A[r][p] = cth * arp - sth * arq;
                    A[r][q] = sth * arp + cth * arq;
                }
                for (int cc = 0; cc < 3; cc++) {
                    float apc = A[p][cc], aqc = A[q][cc];
                    A[p][cc] = cth * apc - sth * aqc;
                    A[q][cc] = sth * apc + cth * aqc;
                }
                for (int r = 0; r < 3; r++) {
                    float vrp = V[r][p], vrq = V[r][q];
                    V[r][p] = cth * vrp - sth * vrq;
                    V[r][q] = sth * vrp + cth * vrq;
                }
            }
    }
    int im = 0;
    if (A[1][1] > A[0][0]) im = 1;
    if (A[2][2] > A[im][im]) im = 2;
    float zx = V[0][im], zy = V[1][im], zz = V[2][im];

    float qx = x[3 * (size_t)T];
    float qy = x[4 * (size_t)T];
    float qz = x[5 * (size_t)T];
    float qw = x[6 * (size_t)T];
    float fx = 2.0f * (qx * qz + qw * qy);
    float fy = 2.0f * (qy * qz - qw * qx);
    float fz = 1.0f - 2.0f * (qx * qx + qy * qy);
    if (fx * zx + fy * zy + fz * zz < 0.0f) { zx = -zx; zy = -zy; zz = -zz; }

    float ux = axis[0], uy = axis[1], uz = axis[2];
    float rx = uy * zz - uz * zy;
    float ry = uz * zx - ux * zz;
    float rz = ux * zy - uy * zx;
    float fwx = ry * uz - rz * uy;
    float fwy = rz * ux - rx * uz;
    float fwz = rx * uy - ry * ux;

    B[0] = rx;  B[1] = ry;  B[2] = rz;
    B[3] = ux;  B[4] = uy;  B[5] = uz;
    B[6] = fwx; B[7] = fwy; B[8] = fwz;
    ref[0] = x[0]; ref[1] = x[(size_t)T]; ref[2] = x[2 * (size_t)T];
}

// ---------------------------------------------------------------------------
// Kernel 1 (R6-proven, 20.3us @ grid 2048): moments reduction rows 0-2
// (default cache -> L2-resident for k3) + Add copy rows 7-9 -> out 3-5.
// ---------------------------------------------------------------------------
__global__ void __launch_bounds__(RTHR) reduce_copy_kernel(
        const float* __restrict__ x, float* __restrict__ out, int T) {
    int n4 = T >> 2;
    const float4* X = (const float4*)x;
    float4* O = (float4*)out;

    float s[9];
#pragma unroll
    for (int k = 0; k < 9; k++) s[k] = 0.f;

    for (int i = blockIdx.x * blockDim.x + threadIdx.x; i < n4;
         i += RBLK * RTHR) {
        float4 a = X[i];
        float4 b = X[n4 + i];
        float4 c = X[2 * n4 + i];
        float4 d = __ldcs(&X[7 * n4 + i]);
        float4 e = __ldcs(&X[8 * n4 + i]);
        float4 f = __ldcs(&X[9 * n4 + i]);
        __stcs(&O[3 * n4 + i], d);
        __stcs(&O[4 * n4 + i], e);
        __stcs(&O[5 * n4 + i], f);
#define ACC(ax, bx, cx)                                   \
        s[0] += (ax); s[1] += (bx); s[2] += (cx);         \
        s[3] += (ax)*(ax); s[4] += (ax)*(bx);             \
        s[5] += (ax)*(cx); s[6] += (bx)*(bx);             \
        s[7] += (bx)*(cx); s[8] += (cx)*(cx);
        ACC(a.x, b.x, c.x); ACC(a.y, b.y, c.y);
        ACC(a.z, b.z, c.z); ACC(a.w, b.w, c.w);
#undef ACC
    }

    int lane = threadIdx.x & 31, wid = threadIdx.x >> 5;
#pragma unroll
    for (int off = 16; off; off >>= 1)
#pragma unroll
        for (int k = 0; k < 9; k++)
            s[k] += __shfl_down_sync(0xffffffffu, s[k], off);

    __shared__ float sh[RTHR / 32][9];
    if (lane == 0)
#pragma unroll
        for (int k = 0; k < 9; k++) sh[wid][k] = s[k];
    __syncthreads();
    if (wid == 0) {
#pragma unroll
        for (int k = 0; k < 9; k++)
            s[k] = (lane < RTHR / 32) ? sh[lane][k] : 0.f;
#pragma unroll
        for (int off = 4; off; off >>= 1)
#pragma unroll
            for (int k = 0; k < 9; k++)
                s[k] += __shfl_down_sync(0xffffffffu, s[k], off);
        if (lane == 0)
#pragma unroll
            for (int k = 0; k < 9; k++)
                g_part[k * RBLK + blockIdx.x] = s[k];   // transposed write
    }
}

// ---------------------------------------------------------------------------
// Kernel 2: tiny solve. PDL gridsync; coalesced partial reads; shuffle-based
// compensated combine (no serial 144-DADD chain); 9 DADDs + Jacobi only.
// ---------------------------------------------------------------------------
__global__ void solve_kernel(const float* __restrict__ x,
                             const float* __restrict__ axis, int T) {
#if __CUDA_ARCH__ >= 900
    cudaGridDependencySynchronize();
#endif
    int tid = threadIdx.x;
    KS acc[9];
#pragma unroll
    for (int k = 0; k < 9; k++) { acc[k].s = 0.f; acc[k].c = 0.f; }

    for (int b = tid; b < RBLK; b += 256)
#pragma unroll
        for (int k = 0; k < 9; k++)
            ks_add(acc[k], __ldcg(&g_part[k * RBLK + b]));   // coalesced per k

    int lane = tid & 31, wid = tid >> 5;
#pragma unroll
    for (int off = 16; off; off >>= 1)
#pragma unroll
        for (int k = 0; k < 9; k++) {
            float s2 = __shfl_down_sync(0xffffffffu, acc[k].s, off);
            float c2 = __shfl_down_sync(0xffffffffu, acc[k].c, off);
            acc[k] = ks_comb(acc[k], s2, c2);
        }

    __shared__ float shs[8][9], shc[8][9];
    __shared__ float fs[9], fc[9];
    if (lane == 0)
#pragma unroll
        for (int k = 0; k < 9; k++) { shs[wid][k] = acc[k].s; shc[wid][k] = acc[k].c; }
    __syncthreads();

    // Cross-warp combine in warp 0 via shuffles (parallel over lanes, no
    // serial fp64): lanes 0-7 hold the 8 warp partials for each k.
    if (wid == 0) {
#pragma unroll
        for (int k = 0; k < 9; k++) {
            KS a;
            a.s = (lane < 8) ? shs[lane][k] : 0.f;
            a.c = (lane < 8) ? shc[lane][k] : 0.f;
#pragma unroll
            for (int off = 4; off; off >>= 1) {
                float s2 = __shfl_down_sync(0xffffffffu, a.s, off);
                float c2 = __shfl_down_sync(0xffffffffu, a.c, off);
                a = ks_comb(a, s2, c2);
            }
            if (lane == 0) { fs[k] = a.s; fc[k] = a.c; }
        }
    }
    __syncthreads();

    if (tid == 0) {
        double S[9];
#pragma unroll
        for (int k = 0; k < 9; k++)
            S[k] = (double)fs[k] + (double)fc[k];    // 9 DADDs only
        float B[9], ref[3];
        solve_basis(S, x, axis, T, B, ref);
#pragma unroll
        for (int k = 0; k < 9; k++) g_B[k] = B[k];
#pragma unroll
        for (int k = 0; k < 3; k++) g_ref[k] = ref[k];
    }
}

// ---------------------------------------------------------------------------
// Kernel 3 (R12-proven, 14.3us): transform rows 0-2 (Xpos via __ldcg,
// mostly L2 hits) -> out rows 0-2. PDL gridsync before using g_B.
// ---------------------------------------------------------------------------
__global__ void __launch_bounds__(RTHR) transform_vec_kernel(
        const float* __restrict__ x, float* __restrict__ out, int T) {
#if __CUDA_ARCH__ >= 900
    cudaGridDependencySynchronize();
#endif
    int n4 = T >> 2;
    int i = blockIdx.x * RTHR + threadIdx.x;
    if (i >= n4) return;

    float b00 = g_B[0], b01 = g_B[1], b02 = g_B[2];
    float b10 = g_B[3], b11 = g_B[4], b12 = g_B[5];
    float b20 = g_B[6], b21 = g_B[7], b22 = g_B[8];
    float r0 = g_ref[0], r1 = g_ref[1], r2 = g_ref[2];

    const float4* X = (const float4*)x;
    float4* O = (float4*)out;

    float4 p0 = __ldcg(&X[i]);
    float4 p1 = __ldcg(&X[n4 + i]);
    float4 p2 = __ldcg(&X[2 * n4 + i]);
    float4 o0, o1, o2;
#define TR(f) {                                           \
    float dx = p0.f - r0, dy = p1.f - r1, dz = p2.f - r2; \
    o0.f = b00 * dx + b01 * dy + b02 * dz;                \
    o1.f = b10 * dx + b11 * dy + b12 * dz;                \
    o2.f = b20 * dx + b21 * dy + b22 * dz; }
    TR(x); TR(y); TR(z); TR(w);
#undef TR
    __stcs(&O[i],          o0);
    __stcs(&O[n4 + i],     o1);
    __stcs(&O[2 * n4 + i], o2);
}

// ---------------------------------------------------------------------------
// Scalar fallback path (T % 4 != 0) — plain launches
// ---------------------------------------------------------------------------
__global__ void reduce_copy_sca_kernel(const float* __restrict__ x,
                                       float* __restrict__ out, int T) {
    size_t sT = (size_t)T;
    float s[9];
#pragma unroll
    for (int k = 0; k < 9; k++) s[k] = 0.f;
    for (int t = blockIdx.x * blockDim.x + threadIdx.x; t < T;
         t += RBLK * RTHR) {
        float ax = x[t], bx = x[sT + t], cx = x[2 * sT + t];
        s[0]+=ax; s[1]+=bx; s[2]+=cx; s[3]+=ax*ax; s[4]+=ax*bx;
        s[5]+=ax*cx; s[6]+=bx*bx; s[7]+=bx*cx; s[8]+=cx*cx;
        out[3 * sT + t] = x[7 * sT + t];
        out[4 * sT + t] = x[8 * sT + t];
        out[5 * sT + t] = x[9 * sT + t];
    }
    int lane = threadIdx.x & 31, wid = threadIdx.x >> 5;
#pragma unroll
    for (int off = 16; off; off >>= 1)
#pragma unroll
        for (int k = 0; k < 9; k++)
            s[k] += __shfl_down_sync(0xffffffffu, s[k], off);
    __shared__ float sh[RTHR / 32][9];
    if (lane == 0)
#pragma unroll
        for (int k = 0; k < 9; k++) sh[wid][k] = s[k];
    __syncthreads();
    if (wid == 0) {
#pragma unroll
        for (int k = 0; k < 9; k++)
            s[k] = (lane < RTHR / 32) ? sh[lane][k] : 0.f;
#pragma unroll
        for (int off = 4; off; off >>= 1)
#pragma unroll
            for (int k = 0; k < 9; k++)
                s[k] += __shfl_down_sync(0xffffffffu, s[k], off);
        if (lane == 0)
#pragma unroll
            for (int k = 0; k < 9; k++)
                g_part[k * RBLK + blockIdx.x] = s[k];
    }
}

__global__ void solve_sca_kernel(const float* __restrict__ x,
                                 const float* __restrict__ axis, int T) {
    int tid = threadIdx.x;
    KS acc[9];
#pragma unroll
    for (int k = 0; k < 9; k++) { acc[k].s = 0.f; acc[k].c = 0.f; }
    for (int b = tid; b < RBLK; b += 256)
#pragma unroll
        for (int k = 0; k < 9; k++)
            ks_add(acc[k], __ldcg(&g_part[k * RBLK + b]));
    int lane = tid & 31, wid = tid >> 5;
#pragma unroll
    for (int off = 16; off; off >>= 1)
#pragma unroll
        for (int k = 0; k < 9; k++) {
            float s2 = __shfl_down_sync(0xffffffffu, acc[k].s, off);
            float c2 = __shfl_down_sync(0xffffffffu, acc[k].c, off);
            acc[k] = ks_comb(acc[k], s2, c2);
        }
    __shared__ float shs[8][9], shc[8][9];
    __shared__ float fs[9], fc[9];
    if (lane == 0)
#pragma unroll
        for (int k = 0; k < 9; k++) { shs[wid][k] = acc[k].s; shc[wid][k] = acc[k].c; }
    __syncthreads();
    if (wid == 0) {
#pragma unroll
        for (int k = 0; k < 9; k++) {
            KS a;
            a.s = (lane < 8) ? shs[lane][k] : 0.f;
            a.c = (lane < 8) ? shc[lane][k] : 0.f;
#pragma unroll
            for (int off = 4; off; off >>= 1) {
                float s2 = __shfl_down_sync(0xffffffffu, a.s, off);
                float c2 = __shfl_down_sync(0xffffffffu, a.c, off);
                a = ks_comb(a, s2, c2);
            }
            if (lane == 0) { fs[k] = a.s; fc[k] = a.c; }
        }
    }
    __syncthreads();
    if (tid == 0) {
        double S[9];
#pragma unroll
        for (int k = 0; k < 9; k++)
            S[k] = (double)fs[k] + (double)fc[k];
        float B[9], ref[3];
        solve_basis(S, x, axis, T, B, ref);
#pragma unroll
        for (int k = 0; k < 9; k++) g_B[k] = B[k];
#pragma unroll
        for (int k = 0; k < 3; k++) g_ref[k] = ref[k];
    }
}

__global__ void transform_sca_kernel(const float* __restrict__ x,
                                     float* __restrict__ out, int T) {
    size_t sT = (size_t)T;
    float b00 = g_B[0], b01 = g_B[1], b02 = g_B[2];
    float b10 = g_B[3], b11 = g_B[4], b12 = g_B[5];
    float b20 = g_B[6], b21 = g_B[7], b22 = g_B[8];
    float r0 = g_ref[0], r1 = g_ref[1], r2 = g_ref[2];
    for (int t = blockIdx.x * blockDim.x + threadIdx.x; t < T;
         t += gridDim.x * blockDim.x) {
        float dx = x[t] - r0, dy = x[sT + t] - r1, dz = x[2 * sT + t] - r2;
        out[t]          = b00 * dx + b01 * dy + b02 * dz;
        out[sT + t]     = b10 * dx + b11 * dy + b12 * dz;
        out[2 * sT + t] = b20 * dx + b21 * dy + b22 * dz;
    }
}

extern "C" void kernel_launch(void* const* d_in, const int* in_sizes, int n_in,
                              void* d_out, int out_size) {
    const float* x = (const float*)d_in[0];
    const float* axis = (const float*)d_in[1];
    int T = in_sizes[0] / 10;

    if ((T & 3) == 0) {
        reduce_copy_kernel<<<RBLK, RTHR>>>(x, (float*)d_out, T);

        // solve: PDL launch (overlaps setup with k1 tail; gridsync gates data)
        {
            cudaLaunchConfig_t cfg = {};
            cfg.gridDim = dim3(1, 1, 1);
            cfg.blockDim = dim3(256, 1, 1);
            cfg.stream = 0;
            cudaLaunchAttribute attr[1];
            attr[0].id = cudaLaunchAttributeProgrammaticStreamSerialization;
            attr[0].val.programmaticStreamSerializationAllowed = 1;
            cfg.attrs = attr;
            cfg.numAttrs = 1;
            cudaLaunchKernelEx(&cfg, solve_kernel, x, axis, T);
        }

        // transform: PDL launch
        {
            int n4 = T >> 2;
            int blocks = (n4 + RTHR - 1) / RTHR;
            cudaLaunchConfig_t cfg = {};
            cfg.gridDim = dim3((unsigned)blocks, 1, 1);
            cfg.blockDim = dim3(RTHR, 1, 1);
            cfg.stream = 0;
            cudaLaunchAttribute attr[1];
            attr[0].id = cudaLaunchAttributeProgrammaticStreamSerialization;
            attr[0].val.programmaticStreamSerializationAllowed = 1;
            cfg.attrs = attr;
            cfg.numAttrs = 1;
            cudaLaunchKernelEx(&cfg, transform_vec_kernel, x, (float*)d_out, T);
        }
    } else {
        reduce_copy_sca_kernel<<<RBLK, RTHR>>>(x, (float*)d_out, T);
        solve_sca_kernel<<<1, 256>>>(x, axis, T);
        int blocks = (T + RTHR - 1) / RTHR;
        if (blocks > 16384) blocks = 16384;
        transform_sca_kernel<<<blocks, RTHR>>>(x, (float*)d_out, T);
    }
}

// round 15
// speedup vs baseline: 1.6086x; 1.0410x over previous
#include <cuda_runtime.h>

#define RBLK 2048
#define RTHR 256

__device__ float g_part[9 * RBLK];   // transposed: [k][block] -> coalesced solve reads
__device__ float g_B[9];
__device__ float g_ref[3];

// ---------------------------------------------------------------------------
// Compensated fp32 accumulation
// ---------------------------------------------------------------------------
struct KS { float s, c; };

__device__ __forceinline__ void ks_add(KS& a, float v) {
    float t  = a.s + v;
    float bp = t - a.s;
    float err = (a.s - (t - bp)) + (v - bp);
    a.c += err;
    a.s  = t;
}
__device__ __forceinline__ KS ks_comb(KS a, float s2, float c2) {
    float t  = a.s + s2;
    float bp = t - a.s;
    float err = (a.s - (t - bp)) + (s2 - bp);
    KS r; r.s = t; r.c = a.c + c2 + err;
    return r;
}

// ---------------------------------------------------------------------------
// Eigensolve: 9 fp64 sums -> basis. Closed-form 3x3 symmetric eigensolver
// on the O(1)-scaled deviator (short serial chain; fp32 throughout).
// ---------------------------------------------------------------------------
__device__ void solve_basis(const double* S, const float* __restrict__ x,
                            const float* __restrict__ axis, int T,
                            float* B /*9*/, float* ref /*3*/) {
    double invT = 1.0 / (double)T;
    double mu0 = S[0] * invT, mu1 = S[1] * invT, mu2 = S[2] * invT;
    double c00d = S[3] - S[0] * mu0;
    double c01d = S[4] - S[0] * mu1;
    double c02d = S[5] - S[0] * mu2;
    double c11d = S[6] - S[1] * mu1;
    double c12d = S[7] - S[1] * mu2;
    double c22d = S[8] - S[2] * mu2;

    // Deviator + scale to O(1): eigenvectors invariant
    double sh3 = (c00d + c11d + c22d) * (1.0 / 3.0);
    double d00 = c00d - sh3, d11 = c11d - sh3, d22 = c22d - sh3;
    double mx = fabs(d00);
    if (fabs(d11) > mx) mx = fabs(d11);
    if (fabs(d22) > mx) mx = fabs(d22);
    if (fabs(c01d) > mx) mx = fabs(c01d);
    if (fabs(c02d) > mx) mx = fabs(c02d);
    if (fabs(c12d) > mx) mx = fabs(c12d);
    double inv = (mx > 0.0) ? (1.0 / mx) : 1.0;

    float a00 = (float)(d00 * inv);
    float a11 = (float)(d11 * inv);
    float a22 = (float)(d22 * inv);
    float a01 = (float)(c01d * inv);
    float a02 = (float)(c02d * inv);
    float a12 = (float)(c12d * inv);

    float zx = 0.f, zy = 0.f, zz = 1.f;   // fallback (isotropic)

    // q = trace/3 (tiny residual), B = A - q I
    float q = (a00 + a11 + a22) * (1.0f / 3.0f);
    float b00 = a00 - q, b11 = a11 - q, b22 = a22 - q;
    float offs = a01 * a01 + a02 * a02 + a12 * a12;
    float p2 = b00 * b00 + b11 * b11 + b22 * b22 + 2.0f * offs;
    if (p2 > 1e-24f) {
        float p = sqrtf(p2 * (1.0f / 6.0f));
        float ip = __frcp_rn(p);
        float e00 = b00 * ip, e11 = b11 * ip, e22 = b22 * ip;
        float e01 = a01 * ip, e02 = a02 * ip, e12 = a12 * ip;
        float detC = e00 * (e11 * e22 - e12 * e12)
                   - e01 * (e01 * e22 - e12 * e02)
                   + e02 * (e01 * e12 - e11 * e02);
        float r = 0.5f * detC;
        r = fminf(1.0f, fmaxf(-1.0f, r));
        float phi = acosf(r) * (1.0f / 3.0f);
        float l1 = q + 2.0f * p * cosf(phi);                  // largest
        float l2 = q + 2.0f * p * cosf(phi + 2.0943951024f);  // smallest of the pair rotations
        float l3 = 3.0f * q - l1 - l2;                        // remaining (trace identity)

        // M = (A - l2 I)(A - l3 I): columns span the l1 eigenspace
        float s23 = l2 + l3, p23 = l2 * l3;
        // A^2 (symmetric)
        float s00 = a00*a00 + a01*a01 + a02*a02;
        float s01 = a00*a01 + a01*a11 + a02*a12;
        float s02 = a00*a02 + a01*a12 + a02*a22;
        float s11 = a01*a01 + a11*a11 + a12*a12;
        float s12 = a01*a02 + a11*a12 + a12*a22;
        float s22 = a02*a02 + a12*a12 + a22*a22;
        float m00 = s00 - s23*a00 + p23;
        float m01 = s01 - s23*a01;
        float m02 = s02 - s23*a02;
        float m11 = s11 - s23*a11 + p23;
        float m12 = s12 - s23*a12;
        float m22 = s22 - s23*a22 + p23;
        // column norms (symmetric: col j = (m0j, m1j, m2j))
        float n0 = m00*m00 + m01*m01 + m02*m02;
        float n1 = m01*m01 + m11*m11 + m12*m12;
        float n2 = m02*m02 + m12*m12 + m22*m22;
        float vx, vy, vz, nn;
        if (n0 >= n1 && n0 >= n2)      { vx = m00; vy = m01; vz = m02; nn = n0; }
        else if (n1 >= n2)             { vx = m01; vy = m11; vz = m12; nn = n1; }
        else                           { vx = m02; vy = m12; vz = m22; nn = n2; }
        if (nn > 1e-30f) {
            float rn = rsqrtf(nn);
            zx = vx * rn; zy = vy * rn; zz = vz * rn;
        }
    }

    // Sign alignment with quaternion forward (raw quat at t=0)
    float qx = x[3 * (size_t)T];
    float qy = x[4 * (size_t)T];
    float qz = x[5 * (size_t)T];
    float qw = x[6 * (size_t)T];
    float fx = 2.0f * (qx * qz + qw * qy);
    float fy = 2.0f * (qy * qz - qw * qx);
    float fz = 1.0f - 2.0f * (qx * qx + qy * qy);
    if (fx * zx + fy * zy + fz * zz < 0.0f) { zx = -zx; zy = -zy; zz = -zz; }

    float ux = axis[0], uy = axis[1], uz = axis[2];
    float rx = uy * zz - uz * zy;
    float ry = uz * zx - ux * zz;
    float rz = ux * zy - uy * zx;
    float fwx = ry * uz - rz * uy;
    float fwy = rz * ux - rx * uz;
    float fwz = rx * uy - ry * ux;

    B[0] = rx;  B[1] = ry;  B[2] = rz;
    B[3] = ux;  B[4] = uy;  B[5] = uz;
    B[6] = fwx; B[7] = fwy; B[8] = fwz;
    ref[0] = x[0]; ref[1] = x[(size_t)T]; ref[2] = x[2 * (size_t)T];
}

// ---------------------------------------------------------------------------
// Kernel 1 (proven 20.5us): moments reduction rows 0-2 (default cache ->
// L2-resident for k3) + Add copy rows 7-9 -> out 3-5 (ldcs/stcs).
// ---------------------------------------------------------------------------
__global__ void __launch_bounds__(RTHR) reduce_copy_kernel(
        const float* __restrict__ x, float* __restrict__ out, int T) {
    int n4 = T >> 2;
    const float4* X = (const float4*)x;
    float4* O = (float4*)out;

    float s[9];
#pragma unroll
    for (int k = 0; k < 9; k++) s[k] = 0.f;

    for (int i = blockIdx.x * blockDim.x + threadIdx.x; i < n4;
         i += RBLK * RTHR) {
        float4 a = X[i];
        float4 b = X[n4 + i];
        float4 c = X[2 * n4 + i];
        float4 d = __ldcs(&X[7 * n4 + i]);
        float4 e = __ldcs(&X[8 * n4 + i]);
        float4 f = __ldcs(&X[9 * n4 + i]);
        __stcs(&O[3 * n4 + i], d);
        __stcs(&O[4 * n4 + i], e);
        __stcs(&O[5 * n4 + i], f);
#define ACC(ax, bx, cx)                                   \
        s[0] += (ax); s[1] += (bx); s[2] += (cx);         \
        s[3] += (ax)*(ax); s[4] += (ax)*(bx);             \
        s[5] += (ax)*(cx); s[6] += (bx)*(bx);             \
        s[7] += (bx)*(cx); s[8] += (cx)*(cx);
        ACC(a.x, b.x, c.x); ACC(a.y, b.y, c.y);
        ACC(a.z, b.z, c.z); ACC(a.w, b.w, c.w);
#undef ACC
    }

    int lane = threadIdx.x & 31, wid = threadIdx.x >> 5;
#pragma unroll
    for (int off = 16; off; off >>= 1)
#pragma unroll
        for (int k = 0; k < 9; k++)
            s[k] += __shfl_down_sync(0xffffffffu, s[k], off);

    __shared__ float sh[RTHR / 32][9];
    if (lane == 0)
#pragma unroll
        for (int k = 0; k < 9; k++) sh[wid][k] = s[k];
    __syncthreads();
    if (wid == 0) {
#pragma unroll
        for (int k = 0; k < 9; k++)
            s[k] = (lane < RTHR / 32) ? sh[lane][k] : 0.f;
#pragma unroll
        for (int off = 4; off; off >>= 1)
#pragma unroll
            for (int k = 0; k < 9; k++)
                s[k] += __shfl_down_sync(0xffffffffu, s[k], off);
        if (lane == 0)
#pragma unroll
            for (int k = 0; k < 9; k++)
                g_part[k * RBLK + blockIdx.x] = s[k];   // transposed write
    }
}

// ---------------------------------------------------------------------------
// Kernel 2: tiny solve (PDL). Coalesced partial reads; shuffle-combine;
// closed-form eigensolver.
// ---------------------------------------------------------------------------
__global__ void solve_kernel(const float* __restrict__ x,
                             const float* __restrict__ axis, int T) {
#if __CUDA_ARCH__ >= 900
    cudaGridDependencySynchronize();
#endif
    int tid = threadIdx.x;
    KS acc[9];
#pragma unroll
    for (int k = 0; k < 9; k++) { acc[k].s = 0.f; acc[k].c = 0.f; }

    for (int b = tid; b < RBLK; b += 256)
#pragma unroll
        for (int k = 0; k < 9; k++)
            ks_add(acc[k], __ldcg(&g_part[k * RBLK + b]));   // coalesced per k

    int lane = tid & 31, wid = tid >> 5;
#pragma unroll
    for (int off = 16; off; off >>= 1)
#pragma unroll
        for (int k = 0; k < 9; k++) {
            float s2 = __shfl_down_sync(0xffffffffu, acc[k].s, off);
            float c2 = __shfl_down_sync(0xffffffffu, acc[k].c, off);
            acc[k] = ks_comb(acc[k], s2, c2);
        }

    __shared__ float shs[8][9], shc[8][9];
    __shared__ float fs[9], fc[9];
    if (lane == 0)
#pragma unroll
        for (int k = 0; k < 9; k++) { shs[wid][k] = acc[k].s; shc[wid][k] = acc[k].c; }
    __syncthreads();

    if (wid == 0) {
#pragma unroll
        for (int k = 0; k < 9; k++) {
            KS a;
            a.s = (lane < 8) ? shs[lane][k] : 0.f;
            a.c = (lane < 8) ? shc[lane][k] : 0.f;
#pragma unroll
            for (int off = 4; off; off >>= 1) {
                float s2 = __shfl_down_sync(0xffffffffu, a.s, off);
                float c2 = __shfl_down_sync(0xffffffffu, a.c, off);
                a = ks_comb(a, s2, c2);
            }
            if (lane == 0) { fs[k] = a.s; fc[k] = a.c; }
        }
    }
    __syncthreads();

    if (tid == 0) {
        double S[9];
#pragma unroll
        for (int k = 0; k < 9; k++)
            S[k] = (double)fs[k] + (double)fc[k];    // 9 DADDs only
        float B[9], ref[3];
        solve_basis(S, x, axis, T, B, ref);
#pragma unroll
        for (int k = 0; k < 9; k++) g_B[k] = B[k];
#pragma unroll
        for (int k = 0; k < 3; k++) g_ref[k] = ref[k];
    }
}

// ---------------------------------------------------------------------------
// Kernel 3 (PDL): transform rows 0-2 -> out 0-2. 2 float4 per stream per
// thread (6 front-batched loads -> deeper MLP; coalesced base/base+RTHR).
// ---------------------------------------------------------------------------
__global__ void __launch_bounds__(RTHR) transform_vec_kernel(
        const float* __restrict__ x, float* __restrict__ out, int T) {
#if __CUDA_ARCH__ >= 900
    cudaGridDependencySynchronize();
#endif
    int n4 = T >> 2;
    int base = blockIdx.x * (RTHR * 2) + threadIdx.x;

    float b00 = g_B[0], b01 = g_B[1], b02 = g_B[2];
    float b10 = g_B[3], b11 = g_B[4], b12 = g_B[5];
    float b20 = g_B[6], b21 = g_B[7], b22 = g_B[8];
    float r0 = g_ref[0], r1 = g_ref[1], r2 = g_ref[2];

    const float4* X = (const float4*)x;
    float4* O = (float4*)out;

    int i0 = base, i1 = base + RTHR;
    bool v0 = i0 < n4, v1 = i1 < n4;

    float4 p0a, p1a, p2a, p0b, p1b, p2b;
    if (v0) { p0a = __ldcg(&X[i0]); p1a = __ldcg(&X[n4 + i0]); p2a = __ldcg(&X[2 * n4 + i0]); }
    if (v1) { p0b = __ldcg(&X[i1]); p1b = __ldcg(&X[n4 + i1]); p2b = __ldcg(&X[2 * n4 + i1]); }

#define TR(p0, p1, p2, o0, o1, o2, f) {                       \
    float dx = p0.f - r0, dy = p1.f - r1, dz = p2.f - r2;     \
    o0.f = b00 * dx + b01 * dy + b02 * dz;                    \
    o1.f = b10 * dx + b11 * dy + b12 * dz;                    \
    o2.f = b20 * dx + b21 * dy + b22 * dz; }

    if (v0) {
        float4 o0, o1, o2;
        TR(p0a, p1a, p2a, o0, o1, o2, x); TR(p0a, p1a, p2a, o0, o1, o2, y);
        TR(p0a, p1a, p2a, o0, o1, o2, z); TR(p0a, p1a, p2a, o0, o1, o2, w);
        __stcs(&O[i0], o0); __stcs(&O[n4 + i0], o1); __stcs(&O[2 * n4 + i0], o2);
    }
    if (v1) {
        float4 o0, o1, o2;
        TR(p0b, p1b, p2b, o0, o1, o2, x); TR(p0b, p1b, p2b, o0, o1, o2, y);
        TR(p0b, p1b, p2b, o0, o1, o2, z); TR(p0b, p1b, p2b, o0, o1, o2, w);
        __stcs(&O[i1], o0); __stcs(&O[n4 + i1], o1); __stcs(&O[2 * n4 + i1], o2);
    }
#undef TR
}

// ---------------------------------------------------------------------------
// Scalar fallback path (T % 4 != 0) — plain launches
// ---------------------------------------------------------------------------
__global__ void reduce_copy_sca_kernel(const float* __restrict__ x,
                                       float* __restrict__ out, int T) {
    size_t sT = (size_t)T;
    float s[9];
#pragma unroll
    for (int k = 0; k < 9; k++) s[k] = 0.f;
    for (int t = blockIdx.x * blockDim.x + threadIdx.x; t < T;
         t += RBLK * RTHR) {
        float ax = x[t], bx = x[sT + t], cx = x[2 * sT + t];
        s[0]+=ax; s[1]+=bx; s[2]+=cx; s[3]+=ax*ax; s[4]+=ax*bx;
        s[5]+=ax*cx; s[6]+=bx*bx; s[7]+=bx*cx; s[8]+=cx*cx;
        out[3 * sT + t] = x[7 * sT + t];
        out[4 * sT + t] = x[8 * sT + t];
        out[5 * sT + t] = x[9 * sT + t];
    }
    int lane = threadIdx.x & 31, wid = threadIdx.x >> 5;
#pragma unroll
    for (int off = 16; off; off >>= 1)
#pragma unroll
        for (int k = 0; k < 9; k++)
            s[k] += __shfl_down_sync(0xffffffffu, s[k], off);
    __shared__ float sh[RTHR / 32][9];
    if (lane == 0)
#pragma unroll
        for (int k = 0; k < 9; k++) sh[wid][k] = s[k];
    __syncthreads();
    if (wid == 0) {
#pragma unroll
        for (int k = 0; k < 9; k++)
            s[k] = (lane < RTHR / 32) ? sh[lane][k] : 0.f;
#pragma unroll
        for (int off = 4; off; off >>= 1)
#pragma unroll
            for (int k = 0; k < 9; k++)
                s[k] += __shfl_down_sync(0xffffffffu, s[k], off);
        if (lane == 0)
#pragma unroll
            for (int k = 0; k < 9; k++)
                g_part[k * RBLK + blockIdx.x] = s[k];
    }
}

__global__ void solve_sca_kernel(const float* __restrict__ x,
                                 const float* __restrict__ axis, int T) {
    int tid = threadIdx.x;
    KS acc[9];
#pragma unroll
    for (int k = 0; k < 9; k++) { acc[k].s = 0.f; acc[k].c = 0.f; }
    for (int b = tid; b < RBLK; b += 256)
#pragma unroll
        for (int k = 0; k < 9; k++)
            ks_add(acc[k], __ldcg(&g_part[k * RBLK + b]));
    int lane = tid & 31, wid = tid >> 5;
#pragma unroll
    for (int off = 16; off; off >>= 1)
#pragma unroll
        for (int k = 0; k < 9; k++) {
            float s2 = __shfl_down_sync(0xffffffffu, acc[k].s, off);
            float c2 = __shfl_down_sync(0xffffffffu, acc[k].c, off);
            acc[k] = ks_comb(acc[k], s2, c2);
        }
    __shared__ float shs[8][9], shc[8][9];
    __shared__ float fs[9], fc[9];
    if (lane == 0)
#pragma unroll
        for (int k = 0; k < 9; k++) { shs[wid][k] = acc[k].s; shc[wid][k] = acc[k].c; }
    __syncthreads();
    if (wid == 0) {
#pragma unroll
        for (int k = 0; k < 9; k++) {
            KS a;
            a.s = (lane < 8) ? shs[lane][k] : 0.f;
            a.c = (lane < 8) ? shc[lane][k] : 0.f;
#pragma unroll
            for (int off = 4; off; off >>= 1) {
                float s2 = __shfl_down_sync(0xffffffffu, a.s, off);
                float c2 = __shfl_down_sync(0xffffffffu, a.c, off);
                a = ks_comb(a, s2, c2);
            }
            if (lane == 0) { fs[k] = a.s; fc[k] = a.c; }
        }
    }
    __syncthreads();
    if (tid == 0) {
        double S[9];
#pragma unroll
        for (int k = 0; k < 9; k++)
            S[k] = (double)fs[k] + (double)fc[k];
        float B[9], ref[3];
        solve_basis(S, x, axis, T, B, ref);
#pragma unroll
        for (int k = 0; k < 9; k++) g_B[k] = B[k];
#pragma unroll
        for (int k = 0; k < 3; k++) g_ref[k] = ref[k];
    }
}

__global__ void transform_sca_kernel(const float* __restrict__ x,
                                     float* __restrict__ out, int T) {
    size_t sT = (size_t)T;
    float b00 = g_B[0], b01 = g_B[1], b02 = g_B[2];
    float b10 = g_B[3], b11 = g_B[4], b12 = g_B[5];
    float b20 = g_B[6], b21 = g_B[7], b22 = g_B[8];
    float r0 = g_ref[0], r1 = g_ref[1], r2 = g_ref[2];
    for (int t = blockIdx.x * blockDim.x + threadIdx.x; t < T;
         t += gridDim.x * blockDim.x) {
        float dx = x[t] - r0, dy = x[sT + t] - r1, dz = x[2 * sT + t] - r2;
        out[t]          = b00 * dx + b01 * dy + b02 * dz;
        out[sT + t]     = b10 * dx + b11 * dy + b12 * dz;
        out[2 * sT + t] = b20 * dx + b21 * dy + b22 * dz;
    }
}

extern "C" void kernel_launch(void* const* d_in, const int* in_sizes, int n_in,
                              void* d_out, int out_size) {
    const float* x = (const float*)d_in[0];
    const float* axis = (const float*)d_in[1];
    int T = in_sizes[0] / 10;

    if ((T & 3) == 0) {
        reduce_copy_kernel<<<RBLK, RTHR>>>(x, (float*)d_out, T);

        {   // solve: PDL launch
            cudaLaunchConfig_t cfg = {};
            cfg.gridDim = dim3(1, 1, 1);
            cfg.blockDim = dim3(256, 1, 1);
            cfg.stream = 0;
            cudaLaunchAttribute attr[1];
            attr[0].id = cudaLaunchAttributeProgrammaticStreamSerialization;
            attr[0].val.programmaticStreamSerializationAllowed = 1;
            cfg.attrs = attr;
            cfg.numAttrs = 1;
            cudaLaunchKernelEx(&cfg, solve_kernel, x, axis, T);
        }

        {   // transform: PDL launch, 2 float4 per stream per thread
            int n4 = T >> 2;
            int blocks = (n4 + RTHR * 2 - 1) / (RTHR * 2);
            cudaLaunchConfig_t cfg = {};
            cfg.gridDim = dim3((unsigned)blocks, 1, 1);
            cfg.blockDim = dim3(RTHR, 1, 1);
            cfg.stream = 0;
            cudaLaunchAttribute attr[1];
            attr[0].id = cudaLaunchAttributeProgrammaticStreamSerialization;
            attr[0].val.programmaticStreamSerializationAllowed = 1;
            cfg.attrs = attr;
            cfg.numAttrs = 1;
            cudaLaunchKernelEx(&cfg, transform_vec_kernel, x, (float*)d_out, T);
        }
    } else {
        reduce_copy_sca_kernel<<<RBLK, RTHR>>>(x, (float*)d_out, T);
        solve_sca_kernel<<<1, 256>>>(x, axis, T);
        int blocks = (T + RTHR - 1) / RTHR;
        if (blocks > 16384) blocks = 16384;
        transform_sca_kernel<<<blocks, RTHR>>>(x, (float*)d_out, T);
    }
}